// round 9
// baseline (speedup 1.0000x reference)
#include <cuda_runtime.h>
#include <cstdint>

// ============================================================================
// out[b,c] = 8192 - sx[b] - sw[c] + 2*cross[b,c]
//   cross = (weighted x bits u8) @ (w bits s8)^T : M=256, N=4096, K=8192
//   legacy mma.sync int8 (rt ~19-20 cyc/SMSP measured R5/R6 -> ~44us GEMM floor).
// R9: fused W-quant with cp.async SMEM STAGING for the f32 weights (fixes
// R8's 217-reg spill blowup). No cross-CTA sync. One barrier per iteration.
// ============================================================================

#define THRESH 0.05f

static constexpr int MDIM = 256;
static constexpr int NDIM = 4096;
static constexpr int FDIM = 4096;
static constexpr int KDIM = 8192;          // bit dim (bytes)

static __device__ __align__(128) uint8_t g_xa[(size_t)MDIM * KDIM]; // 2 MB
static __device__ float g_sx[MDIM];

// ---------------- PTX helpers ------------------------------------------------
__device__ __forceinline__ uint32_t smem_u32(const void* p) {
    uint32_t a;
    asm("{ .reg .u64 t; cvta.to.shared.u64 t, %1; cvt.u32.u64 %0, t; }"
        : "=r"(a) : "l"(p));
    return a;
}

__device__ __forceinline__ void cp16(uint32_t dst, const void* src) {
    asm volatile("cp.async.cg.shared.global [%0], [%1], 16;"
                 :: "r"(dst), "l"(src) : "memory");
}
#define CP_COMMIT() asm volatile("cp.async.commit_group;" ::: "memory")
#define CP_WAIT2()  asm volatile("cp.async.wait_group 2;" ::: "memory")
#define CP_WAIT3()  asm volatile("cp.async.wait_group 3;" ::: "memory")

__device__ __forceinline__ void mma_u8s8(int32_t* c, const uint32_t* a,
                                         const uint32_t* b) {
    asm volatile(
        "mma.sync.aligned.m16n8k32.row.col.s32.u8.s8.s32 "
        "{%0,%1,%2,%3}, {%4,%5,%6,%7}, {%8,%9}, {%0,%1,%2,%3};"
        : "+r"(c[0]), "+r"(c[1]), "+r"(c[2]), "+r"(c[3])
        : "r"(a[0]), "r"(a[1]), "r"(a[2]), "r"(a[3]), "r"(b[0]), "r"(b[1]));
}

__device__ __forceinline__ void ldsm4(uint32_t& r0, uint32_t& r1, uint32_t& r2,
                                      uint32_t& r3, uint32_t addr) {
    asm volatile("ldmatrix.sync.aligned.m8n8.x4.shared.b16 {%0,%1,%2,%3}, [%4];"
                 : "=r"(r0), "=r"(r1), "=r"(r2), "=r"(r3) : "r"(addr));
}

// ---------------- quant packing ----------------------------------------------
// Feature f (mod 4): neg/pos byte weights (128,64),(32,16),(8,4),(2,1).
template <bool WEIGHTED>
__device__ __forceinline__ uint32_t qpack2(float v0, float v1, float wn0,
                                           float wp0, float wn1, float wp1,
                                           float& s) {
    uint32_t b0 = (v0 <= -THRESH) ? (uint32_t)wn0 : 0u;
    uint32_t b1 = (v0 >=  THRESH) ? (uint32_t)wp0 : 0u;
    uint32_t b2 = (v1 <= -THRESH) ? (uint32_t)wn1 : 0u;
    uint32_t b3 = (v1 >=  THRESH) ? (uint32_t)wp1 : 0u;
    s += (float)(b0 + b1 + b2 + b3);
    if (!WEIGHTED) {
        b0 = b0 ? 1u : 0u; b1 = b1 ? 1u : 0u;
        b2 = b2 ? 1u : 0u; b3 = b3 ? 1u : 0u;
    }
    return b0 | (b1 << 8) | (b2 << 16) | (b3 << 24);
}

// ============================================================================
// quant_x: x f32 -> weighted-bit u8 rows in g_xa + row sums (2.5 us, serial).
// ============================================================================
__global__ void __launch_bounds__(256) quant_x_kernel(const float* __restrict__ x) {
    const int row = blockIdx.x;
    const float4* src = (const float4*)(x + (size_t)row * FDIM);
    uint2* dst = (uint2*)(void*)(g_xa + (size_t)row * KDIM);
    float s = 0.0f;
    float4 v[4];
#pragma unroll
    for (int j = 0; j < 4; j++) v[j] = src[threadIdx.x + j * 256];
#pragma unroll
    for (int j = 0; j < 4; j++) {
        uint2 o;
        o.x = qpack2<true>(v[j].x, v[j].y, 128.f, 64.f, 32.f, 16.f, s);
        o.y = qpack2<true>(v[j].z, v[j].w,   8.f,  4.f,  2.f,  1.f, s);
        dst[threadIdx.x + j * 256] = o;
    }
    __shared__ float red[256];
    red[threadIdx.x] = s;
    __syncthreads();
    for (int off = 128; off > 0; off >>= 1) {
        if (threadIdx.x < off) red[threadIdx.x] += red[threadIdx.x + off];
        __syncthreads();
    }
    if (threadIdx.x == 0) g_sx[row] = red[0];
}

// ============================================================================
// Fused: W f32 --cp.async--> SMEM staging (4 slots) --quantize--> B s8 tile
// (double buffer) --ldmatrix/mma--> acc.  BM=64, BN=128, BK=128 B (64 feat).
// 256 thr = 8 warps 2(M) x 4(N), warp tile 32x32. Grid (32,4)=128 CTAs.
// Commit-group schedule: prologue g1{W0} g2{W1,A0} g3{W2,A1} g4{W3,A2};
// iter it commits {A(it+3), W(it+4)}.  wait_group 2 at iter it completes
// everything through the iter-(it-2) group => A(it) and W(it+2) ready, so
// quantizing chunk it+1 and ldsm of stage it are always safe.
// ============================================================================

static constexpr int BM = 64;
static constexpr int BN = 128;
static constexpr int BK = 128;                  // bytes per chunk (64 features)
static constexpr int KITERS = KDIM / BK;        // 64
static constexpr int NSTAGES = 4;               // A pipeline depth
static constexpr int STRIDE = 144;
static constexpr int A_STG = BM * STRIDE;       // 9216
static constexpr int A_REG = NSTAGES * A_STG;   // 36864
static constexpr int B_SZ = BN * STRIDE;        // 18432
static constexpr int WS_OFF = A_REG + 2 * B_SZ; // 73728
static constexpr int WSLOT = BN * 64 * 4;       // 32768 (128 rows x 64 f32)
static constexpr int SMEM_BYTES = WS_OFF + 4 * WSLOT;  // 204800

__global__ void __launch_bounds__(256, 1)
fused_kernel(const float* __restrict__ w, float* __restrict__ out) {
    extern __shared__ char smem[];
    __shared__ float swacc[BN];

    const uint32_t sb = smem_u32(smem);
    const int tid = threadIdx.x;
    const int wid = tid >> 5;
    const int lane = tid & 31;
    const int wm = wid & 1;
    const int wn = wid >> 1;
    const int n0 = blockIdx.x * BN;
    const int m0 = blockIdx.y * BM;

    // ---- W staging cp.async: 32 KB/chunk, 8 x 16B per thread ---------------
    const float* wbase = w + (size_t)n0 * FDIM;
    auto stage_w = [&](int c) {
        if (c >= KITERS) return;
        const uint32_t dst0 = sb + (uint32_t)(WS_OFF + (c & 3) * WSLOT);
#pragma unroll
        for (int i = 0; i < 8; i++) {
            const int q = i * 256 + tid;          // 16B-chunk index 0..2047
            const int row = q >> 4, c16 = q & 15; // 16 chunks of 16B per row
            cp16(dst0 + (uint32_t)(row * 256 + c16 * 16),
                 wbase + (size_t)row * FDIM + c * 64 + c16 * 4);
        }
    };

    // ---- quantize one staged chunk -> B s8 buffer --------------------------
    const int qrow = tid >> 1;                    // B row 0..127
    const int qh   = tid & 1;                     // 32-feature half
    const int l7   = tid & 7;                     // LDS swizzle key
    const uint32_t qsrc0 = (uint32_t)(WS_OFF + qrow * 256 + qh * 128);
    const uint32_t qdst0 = (uint32_t)(A_REG + qrow * STRIDE + qh * 64);
    float swsum = 0.0f;
    auto quant_chunk = [&](int c, int buf) {
        const uint32_t src = sb + qsrc0 + (uint32_t)((c & 3) * WSLOT);
        uint2 o[8];
#pragma unroll
        for (int j = 0; j < 8; j++) {
            const int jj = j ^ l7;                // conflict-free LDS order
            float4 q = *(const float4*)(smem + (src - sb) + jj * 16);
            uint2 t;
            t.x = qpack2<false>(q.x, q.y, 128.f, 64.f, 32.f, 16.f, swsum);
            t.y = qpack2<false>(q.z, q.w,   8.f,  4.f,  2.f,  1.f, swsum);
            o[jj] = t;
        }
        char* d = smem + qdst0 + buf * B_SZ;
#pragma unroll
        for (int k = 0; k < 4; k++) {
            uint4 v;
            v.x = o[2*k].x;  v.y = o[2*k].y;
            v.z = o[2*k+1].x; v.w = o[2*k+1].y;
            *(uint4*)(d + 16 * k) = v;
        }
    };

    // ---- A cp.async: 64 rows x 8 x 16B = 512 chunks -> 2 per thread --------
    const uint8_t* a_src[2]; uint32_t a_dst[2];
#pragma unroll
    for (int i = 0; i < 2; i++) {
        int q = tid + i * 256;
        int r = q >> 3, kc = q & 7;
        a_src[i] = g_xa + (size_t)(m0 + r) * KDIM + kc * 16;
        a_dst[i] = (uint32_t)(r * STRIDE + kc * 16);
    }
    auto load_a = [&](int s) {
        if (s >= KITERS) return;
        const uint32_t base = sb + (uint32_t)(s & (NSTAGES - 1)) * A_STG;
        const int ko = s * BK;
#pragma unroll
        for (int i = 0; i < 2; i++) cp16(base + a_dst[i], a_src[i] + ko);
    };

    // ---- ldmatrix offsets ---------------------------------------------------
    const int g  = lane >> 3;
    const int lr = lane & 7;
    uint32_t a_lds[2];
#pragma unroll
    for (int mf = 0; mf < 2; mf++)
        a_lds[mf] = (uint32_t)((wm * 32 + mf * 16 + lr + (g & 1) * 8) * STRIDE
                               + (g >> 1) * 16);
    uint32_t b_lds[2];
#pragma unroll
    for (int p = 0; p < 2; p++)
        b_lds[p] = (uint32_t)(A_REG + (wn * 32 + p * 16 + lr + (g >> 1) * 8) * STRIDE
                              + (g & 1) * 16);

    int32_t acc[2][4][4];
#pragma unroll
    for (int mf = 0; mf < 2; mf++)
#pragma unroll
        for (int nf = 0; nf < 4; nf++)
#pragma unroll
            for (int r = 0; r < 4; r++) acc[mf][nf][r] = 0;

    // ---- prologue: groups g1{W0} g2{W1,A0} g3{W2,A1} g4{W3,A2} -------------
    stage_w(0);            CP_COMMIT();
    stage_w(1); load_a(0); CP_COMMIT();
    stage_w(2); load_a(1); CP_COMMIT();
    stage_w(3); load_a(2); CP_COMMIT();
    CP_WAIT3();            // g1 done: W0 staged
    __syncthreads();
    quant_chunk(0, 0);     // B chunk 0 -> buf 0

    // ---- mainloop -----------------------------------------------------------
    for (int it = 0; it < KITERS; ++it) {
        CP_WAIT2();        // A(it), W(it+2) and older all landed
        __syncthreads();   // visibility + prev math done (buffers released)

        if (it + 1 < KITERS) quant_chunk(it + 1, (it + 1) & 1);
        load_a(it + 3); stage_w(it + 4); CP_COMMIT();

        const uint32_t sbase = sb + (uint32_t)(it & (NSTAGES - 1)) * A_STG;
        const uint32_t bbase = sb + (uint32_t)(it & 1) * B_SZ;
        uint32_t afr[2][4], bfr[4][2];
#pragma unroll
        for (int ks = 0; ks < BK / 32; ++ks) {
            const uint32_t kb = (uint32_t)(ks * 32);
#pragma unroll
            for (int mf = 0; mf < 2; mf++)
                ldsm4(afr[mf][0], afr[mf][1], afr[mf][2], afr[mf][3],
                      sbase + a_lds[mf] + kb);
#pragma unroll
            for (int p = 0; p < 2; p++)
                ldsm4(bfr[2*p][0], bfr[2*p][1], bfr[2*p+1][0], bfr[2*p+1][1],
                      bbase + b_lds[p] + kb);
#pragma unroll
            for (int mf = 0; mf < 2; mf++)
#pragma unroll
                for (int nf = 0; nf < 4; nf++)
                    mma_u8s8(acc[mf][nf], afr[mf], bfr[nf]);
        }
    }

    // ---- sw: pair (t, t^1) covers a full row over all 64 chunks ------------
    swsum += __shfl_xor_sync(0xffffffffu, swsum, 1);
    if ((tid & 1) == 0) swacc[qrow] = swsum;
    __syncthreads();

    // ---- epilogue: out = 8192 - sx[m] - sw[n] + 2*acc  (exact) -------------
#pragma unroll
    for (int mf = 0; mf < 2; mf++) {
        const int r0 = m0 + wm * 32 + mf * 16 + (lane >> 2);
        const float bx0 = 8192.0f - g_sx[r0];
        const float bx1 = 8192.0f - g_sx[r0 + 8];
#pragma unroll
        for (int nf = 0; nf < 4; nf++) {
            const int cl = wn * 32 + nf * 8 + (lane & 3) * 2;
            const float sw0 = swacc[cl], sw1 = swacc[cl + 1];
            const int col = n0 + cl;
            float2 v0, v1;
            v0.x = bx0 - sw0 + 2.0f * (float)acc[mf][nf][0];
            v0.y = bx0 - sw1 + 2.0f * (float)acc[mf][nf][1];
            v1.x = bx1 - sw0 + 2.0f * (float)acc[mf][nf][2];
            v1.y = bx1 - sw1 + 2.0f * (float)acc[mf][nf][3];
            *(float2*)(out + (size_t)r0 * NDIM + col) = v0;
            *(float2*)(out + (size_t)(r0 + 8) * NDIM + col) = v1;
        }
    }
}

// ============================================================================
// launcher
// ============================================================================
extern "C" void kernel_launch(void* const* d_in, const int* in_sizes, int n_in,
                              void* d_out, int out_size) {
    (void)in_sizes; (void)n_in; (void)out_size;
    const float* x = (const float*)d_in[0];   // [256, 4096]
    const float* w = (const float*)d_in[1];   // [4096, 4096]
    float* out = (float*)d_out;               // [256, 4096]

    quant_x_kernel<<<MDIM, 256>>>(x);

    cudaFuncSetAttribute(fused_kernel,
                         cudaFuncAttributeMaxDynamicSharedMemorySize, SMEM_BYTES);
    dim3 grid(NDIM / BN, MDIM / BM);          // (32, 4) = 128 CTAs
    fused_kernel<<<grid, 256, SMEM_BYTES>>>(w, out);
}

// round 10
// speedup vs baseline: 3.5969x; 3.5969x over previous
#include <cuda_runtime.h>
#include <cstdint>

// ============================================================================
// out[b,c] = 8192 - sx[b] - sw[c] + 2*cross[b,c]
//   cross = (weighted x bits u8) @ (w bits s8)^T : M=256, N=4096, K=8192
//   legacy mma.sync int8. Fusion abandoned (R8/R9 failed); split design.
// R10: GEMM mainloop processes 256B of K per barrier (32 barriers, not 64),
// 3 double-stages of smem (166 KB), halving the per-iteration pipeline bubble.
// ============================================================================

#define THRESH 0.05f

static constexpr int MDIM = 256;
static constexpr int NDIM = 4096;
static constexpr int FDIM = 4096;
static constexpr int KDIM = 8192;     // bit dim (bytes)

// ---------------- scratch (device globals) -----------------------------------
static __device__ __align__(128) uint8_t g_xa[(size_t)MDIM * KDIM]; // 2 MB
static __device__ __align__(128) uint8_t g_wb[(size_t)NDIM * KDIM]; // 32 MB
static __device__ float g_sx[MDIM];
static __device__ float g_sw[NDIM];

// ---------------- PTX helpers ------------------------------------------------
__device__ __forceinline__ uint32_t smem_u32(const void* p) {
    uint32_t a;
    asm("{ .reg .u64 t; cvta.to.shared.u64 t, %1; cvt.u32.u64 %0, t; }"
        : "=r"(a) : "l"(p));
    return a;
}

__device__ __forceinline__ void cp16(uint32_t dst, const void* src) {
    asm volatile("cp.async.cg.shared.global [%0], [%1], 16;"
                 :: "r"(dst), "l"(src) : "memory");
}
#define CP_COMMIT() asm volatile("cp.async.commit_group;" ::: "memory")
#define CP_WAIT1()  asm volatile("cp.async.wait_group 1;" ::: "memory")

__device__ __forceinline__ void mma_u8s8(int32_t* c, const uint32_t* a,
                                         const uint32_t* b) {
    asm volatile(
        "mma.sync.aligned.m16n8k32.row.col.s32.u8.s8.s32 "
        "{%0,%1,%2,%3}, {%4,%5,%6,%7}, {%8,%9}, {%0,%1,%2,%3};"
        : "+r"(c[0]), "+r"(c[1]), "+r"(c[2]), "+r"(c[3])
        : "r"(a[0]), "r"(a[1]), "r"(a[2]), "r"(a[3]), "r"(b[0]), "r"(b[1]));
}

__device__ __forceinline__ void ldsm4(uint32_t& r0, uint32_t& r1, uint32_t& r2,
                                      uint32_t& r3, uint32_t addr) {
    asm volatile("ldmatrix.sync.aligned.m8n8.x4.shared.b16 {%0,%1,%2,%3}, [%4];"
                 : "=r"(r0), "=r"(r1), "=r"(r2), "=r"(r3) : "r"(addr));
}

// ---------------- quant packing ----------------------------------------------
// Feature f (mod 4): neg/pos byte weights (128,64),(32,16),(8,4),(2,1).
template <bool WEIGHTED>
__device__ __forceinline__ uint32_t qpack2(float v0, float v1, float wn0,
                                           float wp0, float wn1, float wp1,
                                           float& s) {
    uint32_t b0 = (v0 <= -THRESH) ? (uint32_t)wn0 : 0u;
    uint32_t b1 = (v0 >=  THRESH) ? (uint32_t)wp0 : 0u;
    uint32_t b2 = (v1 <= -THRESH) ? (uint32_t)wn1 : 0u;
    uint32_t b3 = (v1 >=  THRESH) ? (uint32_t)wp1 : 0u;
    s += (float)(b0 + b1 + b2 + b3);
    if (!WEIGHTED) {
        b0 = b0 ? 1u : 0u; b1 = b1 ? 1u : 0u;
        b2 = b2 ? 1u : 0u; b3 = b3 ? 1u : 0u;
    }
    return b0 | (b1 << 8) | (b2 << 16) | (b3 << 24);
}

template <bool WEIGHTED>
__device__ __forceinline__ void quant_row(const float* __restrict__ src_row,
                                          uint8_t* __restrict__ dst_row,
                                          float* __restrict__ sum_out) {
    const float4* src = (const float4*)src_row;
    uint2* dst = (uint2*)(void*)dst_row;
    float s = 0.0f;
    float4 v[4];
#pragma unroll
    for (int j = 0; j < 4; j++) v[j] = src[threadIdx.x + j * 256];
#pragma unroll
    for (int j = 0; j < 4; j++) {
        uint2 o;
        o.x = qpack2<WEIGHTED>(v[j].x, v[j].y, 128.f, 64.f, 32.f, 16.f, s);
        o.y = qpack2<WEIGHTED>(v[j].z, v[j].w,   8.f,  4.f,  2.f,  1.f, s);
        dst[threadIdx.x + j * 256] = o;
    }
    __shared__ float red[256];
    red[threadIdx.x] = s;
    __syncthreads();
    for (int off = 128; off > 0; off >>= 1) {
        if (threadIdx.x < off) red[threadIdx.x] += red[threadIdx.x + off];
        __syncthreads();
    }
    if (threadIdx.x == 0) *sum_out = red[0];
}

__global__ void __launch_bounds__(256) quant_kernel(const float* __restrict__ x,
                                                    const float* __restrict__ w) {
    const int bid = blockIdx.x;
    if (bid < MDIM) {
        quant_row<true>(x + (size_t)bid * FDIM, g_xa + (size_t)bid * KDIM,
                        &g_sx[bid]);
    } else {
        const int row = bid - MDIM;
        quant_row<false>(w + (size_t)row * FDIM, g_wb + (size_t)row * KDIM,
                         &g_sw[row]);
    }
}

// ============================================================================
// int8 GEMM: BM=64, BN=128; double-chunk iterations (DK=256 B per barrier).
// 3 double-stages x 55.3 KB = 166 KB smem. 256 thr = 8 warps 2(M) x 4(N),
// warp tile 32x32, SMEM stride 144 B (ldmatrix conflict-free).
// Grid (32, 4) = 128 CTAs, 1/SM, single wave.
// ============================================================================

static constexpr int BM = 64;
static constexpr int BN = 128;
static constexpr int HK = 128;                  // half-chunk bytes
static constexpr int DITERS = KDIM / (2 * HK);  // 32 double-iterations
static constexpr int NDSTG = 3;                 // double-stage count
static constexpr int STRIDE = 144;
static constexpr int A_SZ = BM * STRIDE;        // 9216
static constexpr int B_SZ = BN * STRIDE;        // 18432
static constexpr int HSTG = A_SZ + B_SZ;        // 27648 (half-stage)
static constexpr int DSTG = 2 * HSTG;           // 55296
static constexpr int SMEM_BYTES = NDSTG * DSTG; // 165888

__global__ void __launch_bounds__(256, 1)
qgemm_kernel(float* __restrict__ out) {
    extern __shared__ char smem[];
    const uint32_t sb = smem_u32(smem);
    const int tid = threadIdx.x;
    const int wid = tid >> 5;
    const int lane = tid & 31;
    const int wm = wid & 1;
    const int wn = wid >> 1;
    const int n0 = blockIdx.x * BN;
    const int m0 = blockIdx.y * BM;

    // ---- cp.async assignments (per half-stage): A 2/thr, B 4/thr -----------
    const uint8_t* a_src[2]; uint32_t a_dst[2];
#pragma unroll
    for (int i = 0; i < 2; i++) {
        int q = tid + i * 256;
        int r = q >> 3, kc = q & 7;
        a_src[i] = g_xa + (size_t)(m0 + r) * KDIM + kc * 16;
        a_dst[i] = (uint32_t)(r * STRIDE + kc * 16);
    }
    const uint8_t* b_src[4]; uint32_t b_dst[4];
#pragma unroll
    for (int i = 0; i < 4; i++) {
        int q = tid + i * 256;
        int r = q >> 3, kc = q & 7;
        b_src[i] = g_wb + (size_t)(n0 + r) * KDIM + kc * 16;
        b_dst[i] = (uint32_t)(A_SZ + r * STRIDE + kc * 16);
    }

    // load one DOUBLE stage d (k bytes [d*256, d*256+256)), commit as 1 group
    auto load_dstage = [&](int d) {
        const uint32_t base = sb + (uint32_t)(d % NDSTG) * DSTG;
#pragma unroll
        for (int h = 0; h < 2; h++) {
            const int ko = d * 2 * HK + h * HK;
            const uint32_t hb = base + (uint32_t)h * HSTG;
#pragma unroll
            for (int i = 0; i < 2; i++) cp16(hb + a_dst[i], a_src[i] + ko);
#pragma unroll
            for (int i = 0; i < 4; i++) cp16(hb + b_dst[i], b_src[i] + ko);
        }
    };

    // ---- ldmatrix per-lane offsets (within a half-stage) -------------------
    const int g  = lane >> 3;
    const int lr = lane & 7;
    uint32_t a_lds[2];
#pragma unroll
    for (int mf = 0; mf < 2; mf++)
        a_lds[mf] = (uint32_t)((wm * 32 + mf * 16 + lr + (g & 1) * 8) * STRIDE
                               + (g >> 1) * 16);
    uint32_t b_lds[2];
#pragma unroll
    for (int p = 0; p < 2; p++)
        b_lds[p] = (uint32_t)(A_SZ + (wn * 32 + p * 16 + lr + (g >> 1) * 8) * STRIDE
                              + (g & 1) * 16);

    int32_t acc[2][4][4];
#pragma unroll
    for (int mf = 0; mf < 2; mf++)
#pragma unroll
        for (int nf = 0; nf < 4; nf++)
#pragma unroll
            for (int r = 0; r < 4; r++) acc[mf][nf][r] = 0;

    // ---- prologue: double-stages 0,1 in flight -----------------------------
    load_dstage(0); CP_COMMIT();
    load_dstage(1); CP_COMMIT();

    // ---- mainloop: one barrier per 256B of K -------------------------------
    for (int d = 0; d < DITERS; ++d) {
        CP_WAIT1();          // double-stage d landed (this thread's part)
        __syncthreads();     // whole tile visible; buffer (d+2)%3 free

        if (d + 2 < DITERS) load_dstage(d + 2);
        CP_COMMIT();

        const uint32_t dbase = sb + (uint32_t)(d % NDSTG) * DSTG;
#pragma unroll
        for (int h = 0; h < 2; h++) {            // two half-chunks
            const uint32_t hbase = dbase + (uint32_t)h * HSTG;
            uint32_t afr[2][4], bfr[4][2];
#pragma unroll
            for (int ks = 0; ks < HK / 32; ++ks) {   // 4 k-steps of 32
                const uint32_t kb = (uint32_t)(ks * 32);
#pragma unroll
                for (int mf = 0; mf < 2; mf++)
                    ldsm4(afr[mf][0], afr[mf][1], afr[mf][2], afr[mf][3],
                          hbase + a_lds[mf] + kb);
#pragma unroll
                for (int p = 0; p < 2; p++)
                    ldsm4(bfr[2*p][0], bfr[2*p][1], bfr[2*p+1][0], bfr[2*p+1][1],
                          hbase + b_lds[p] + kb);
#pragma unroll
                for (int mf = 0; mf < 2; mf++)
#pragma unroll
                    for (int nf = 0; nf < 4; nf++)
                        mma_u8s8(acc[mf][nf], afr[mf], bfr[nf]);
            }
        }
    }

    // ---- epilogue: out = 8192 - sx[m] - sw[n] + 2*acc  (exact integers) ----
#pragma unroll
    for (int mf = 0; mf < 2; mf++) {
        const int r0 = m0 + wm * 32 + mf * 16 + (lane >> 2);
        const float bx0 = 8192.0f - g_sx[r0];
        const float bx1 = 8192.0f - g_sx[r0 + 8];
#pragma unroll
        for (int nf = 0; nf < 4; nf++) {
            const int col = n0 + wn * 32 + nf * 8 + (lane & 3) * 2;
            const float sw0 = g_sw[col], sw1 = g_sw[col + 1];
            float2 v0, v1;
            v0.x = bx0 - sw0 + 2.0f * (float)acc[mf][nf][0];
            v0.y = bx0 - sw1 + 2.0f * (float)acc[mf][nf][1];
            v1.x = bx1 - sw0 + 2.0f * (float)acc[mf][nf][2];
            v1.y = bx1 - sw1 + 2.0f * (float)acc[mf][nf][3];
            *(float2*)(out + (size_t)r0 * NDIM + col) = v0;
            *(float2*)(out + (size_t)(r0 + 8) * NDIM + col) = v1;
        }
    }
}

// ============================================================================
// launcher
// ============================================================================
extern "C" void kernel_launch(void* const* d_in, const int* in_sizes, int n_in,
                              void* d_out, int out_size) {
    (void)in_sizes; (void)n_in; (void)out_size;
    const float* x = (const float*)d_in[0];   // [256, 4096]
    const float* w = (const float*)d_in[1];   // [4096, 4096]
    float* out = (float*)d_out;               // [256, 4096]

    quant_kernel<<<MDIM + NDIM, 256>>>(x, w);

    cudaFuncSetAttribute(qgemm_kernel,
                         cudaFuncAttributeMaxDynamicSharedMemorySize, SMEM_BYTES);
    dim3 grid(NDIM / BN, MDIM / BM);          // (32, 4) = 128 CTAs
    qgemm_kernel<<<grid, 256, SMEM_BYTES>>>(out);
}